// round 2
// baseline (speedup 1.0000x reference)
#include <cuda_runtime.h>
#include <math.h>

#define D_MODEL 1024
#define SEQ     2048
#define BATCH   2
#define NROWS   (BATCH*SEQ)   /* 4096 */
#define DFF     4096
#define NHEAD   16
#define HDIM    64

// -------------------- scratch (device globals; no allocs allowed) ------------
__device__ float g_ln [NROWS*D_MODEL];
__device__ float g_q  [NROWS*D_MODEL];
__device__ float g_k  [NROWS*D_MODEL];
__device__ float g_v  [NROWS*D_MODEL];
__device__ float g_ctx[NROWS*D_MODEL];
__device__ float g_h  [NROWS*DFF];

// -------------------- LayerNorm (ddof=1, eps=1e-12) --------------------------
__device__ __forceinline__ float blockSum(float v, float* red, int tid) {
    #pragma unroll
    for (int o = 16; o; o >>= 1) v += __shfl_xor_sync(0xffffffffu, v, o);
    if ((tid & 31) == 0) red[tid >> 5] = v;
    __syncthreads();
    if (tid < 8) {
        v = red[tid];
        #pragma unroll
        for (int o = 4; o; o >>= 1) v += __shfl_xor_sync(0xffu, v, o);
        if (tid == 0) red[0] = v;
    }
    __syncthreads();
    float r = red[0];
    __syncthreads();
    return r;
}

__global__ void ln_kernel(const float* __restrict__ x,
                          const float* __restrict__ gamma,
                          const float* __restrict__ beta,
                          float* __restrict__ y) {
    __shared__ float red[8];
    int row = blockIdx.x, tid = threadIdx.x;      // 256 threads, D=1024 -> 1 float4/thread
    const float4* x4 = (const float4*)(x + (size_t)row * D_MODEL);
    float4 v = x4[tid];
    float s = v.x + v.y + v.z + v.w;
    float tot = blockSum(s, red, tid);
    float mean = tot * (1.0f / D_MODEL);
    float dx0 = v.x - mean, dx1 = v.y - mean, dx2 = v.z - mean, dx3 = v.w - mean;
    float sq = dx0*dx0 + dx1*dx1 + dx2*dx2 + dx3*dx3;
    float tots = blockSum(sq, red, tid);
    float var = tots * (1.0f / (D_MODEL - 1));    // ddof = 1
    float inv = rsqrtf(var + 1e-12f);
    float4 gv = ((const float4*)gamma)[tid];
    float4 bv = ((const float4*)beta)[tid];
    float4 o;
    o.x = gv.x * dx0 * inv + bv.x;
    o.y = gv.y * dx1 * inv + bv.y;
    o.z = gv.z * dx2 * inv + bv.z;
    o.w = gv.w * dx3 * inv + bv.w;
    ((float4*)(y + (size_t)row * D_MODEL))[tid] = o;
}

// -------------------- tiled fp32 GEMM: C = A(MxK) @ B(KxN) + bias [+res][gelu]
#define BM 128
#define BN 128
#define BK 16

__device__ __forceinline__ float gelu_f(float x) {
    float x3 = x * x * x;
    return 0.5f * x * (1.0f + tanhf(0.7978845608028654f * (x + 0.044715f * x3)));
}

template<bool GELU, bool RES>
__global__ void __launch_bounds__(256)
gemm_kernel(const float* __restrict__ A, const float* __restrict__ B,
            const float* __restrict__ bias, const float* __restrict__ res,
            float* __restrict__ C, int M, int N, int K) {
    __shared__ float As[BK][BM + 4];
    __shared__ float Bs[BK][BN + 4];
    int tid = threadIdx.x;
    int tx = tid & 15, ty = tid >> 4;
    int row0 = blockIdx.y * BM, col0 = blockIdx.x * BN;

    float acc[8][8];
    #pragma unroll
    for (int i = 0; i < 8; i++)
        #pragma unroll
        for (int j = 0; j < 8; j++) acc[i][j] = 0.0f;

    for (int k0 = 0; k0 < K; k0 += BK) {
        // A tile: 128x16 = 512 float4, 2 per thread (store transposed)
        #pragma unroll
        for (int t = 0; t < 2; t++) {
            int f = tid + t * 256;
            int r = f >> 2, cv = (f & 3) << 2;
            float4 a = *(const float4*)&A[(size_t)(row0 + r) * K + k0 + cv];
            As[cv + 0][r] = a.x; As[cv + 1][r] = a.y;
            As[cv + 2][r] = a.z; As[cv + 3][r] = a.w;
        }
        // B tile: 16x128 = 512 float4, 2 per thread
        #pragma unroll
        for (int t = 0; t < 2; t++) {
            int f = tid + t * 256;
            int r = f >> 5, cv = (f & 31) << 2;
            *(float4*)&Bs[r][cv] = *(const float4*)&B[(size_t)(k0 + r) * N + col0 + cv];
        }
        __syncthreads();
        #pragma unroll
        for (int kk = 0; kk < BK; kk++) {
            float a[8], b[8];
            *(float4*)&a[0] = *(const float4*)&As[kk][ty * 8];
            *(float4*)&a[4] = *(const float4*)&As[kk][ty * 8 + 4];
            *(float4*)&b[0] = *(const float4*)&Bs[kk][tx * 8];
            *(float4*)&b[4] = *(const float4*)&Bs[kk][tx * 8 + 4];
            #pragma unroll
            for (int i = 0; i < 8; i++)
                #pragma unroll
                for (int j = 0; j < 8; j++)
                    acc[i][j] += a[i] * b[j];
        }
        __syncthreads();
    }

    #pragma unroll
    for (int i = 0; i < 8; i++) {
        int r = row0 + ty * 8 + i;
        #pragma unroll
        for (int j = 0; j < 8; j += 4) {
            int c = col0 + tx * 8 + j;
            float4 o;
            o.x = acc[i][j + 0] + bias[c + 0];
            o.y = acc[i][j + 1] + bias[c + 1];
            o.z = acc[i][j + 2] + bias[c + 2];
            o.w = acc[i][j + 3] + bias[c + 3];
            if (GELU) { o.x = gelu_f(o.x); o.y = gelu_f(o.y); o.z = gelu_f(o.z); o.w = gelu_f(o.w); }
            if (RES) {
                float4 rr = *(const float4*)&res[(size_t)r * N + c];
                o.x += rr.x; o.y += rr.y; o.z += rr.z; o.w += rr.w;
            }
            *(float4*)&C[(size_t)r * N + c] = o;
        }
    }
}

// -------------------- causal flash attention, fp32, 64q x 64k tiles ----------
#define ATT_PAD 68
#define ATTN_SMEM (4 * 64 * ATT_PAD * (int)sizeof(float))

__global__ void __launch_bounds__(256)
attn_kernel(const float* __restrict__ Q, const float* __restrict__ K,
            const float* __restrict__ V, float* __restrict__ O) {
    extern __shared__ float sm[];
    float* Qt = sm;                     // [dim][query]  64 x 68
    float* Kt = sm + 64 * ATT_PAD;      // [dim][key]
    float* Vs = sm + 2 * 64 * ATT_PAD;  // [key][dim]
    float* Ps = sm + 3 * 64 * ATT_PAD;  // [query][key]

    int tid = threadIdx.x;
    int tx = tid & 15, ty = tid >> 4;
    int qt = blockIdx.x, bh = blockIdx.y;
    int b = bh >> 4, h = bh & 15;
    size_t base = (size_t)b * SEQ * D_MODEL + (size_t)h * HDIM;
    int qbase = qt * 64;

    // load Q tile transposed: [dim][query]
    #pragma unroll
    for (int t = 0; t < 4; t++) {
        int f = tid + t * 256;
        int r = f >> 4, cv = (f & 15) << 2;
        float4 q = *(const float4*)&Q[base + (size_t)(qbase + r) * D_MODEL + cv];
        Qt[(cv + 0) * ATT_PAD + r] = q.x; Qt[(cv + 1) * ATT_PAD + r] = q.y;
        Qt[(cv + 2) * ATT_PAD + r] = q.z; Qt[(cv + 3) * ATT_PAD + r] = q.w;
    }

    float m[4], l[4], o[4][4];
    #pragma unroll
    for (int i = 0; i < 4; i++) {
        m[i] = -1e30f; l[i] = 0.0f;
        #pragma unroll
        for (int j = 0; j < 4; j++) o[i][j] = 0.0f;
    }

    for (int kt = 0; kt <= qt; kt++) {
        int kbase = kt * 64;
        __syncthreads();   // protect Kt/Vs/Ps reuse
        #pragma unroll
        for (int t = 0; t < 4; t++) {
            int f = tid + t * 256;
            int r = f >> 4, cv = (f & 15) << 2;
            float4 kv = *(const float4*)&K[base + (size_t)(kbase + r) * D_MODEL + cv];
            Kt[(cv + 0) * ATT_PAD + r] = kv.x; Kt[(cv + 1) * ATT_PAD + r] = kv.y;
            Kt[(cv + 2) * ATT_PAD + r] = kv.z; Kt[(cv + 3) * ATT_PAD + r] = kv.w;
            float4 vv = *(const float4*)&V[base + (size_t)(kbase + r) * D_MODEL + cv];
            *(float4*)&Vs[r * ATT_PAD + cv] = vv;
        }
        __syncthreads();

        // scores: S[4q][4k] = Q . K
        float s[4][4];
        #pragma unroll
        for (int i = 0; i < 4; i++)
            #pragma unroll
            for (int j = 0; j < 4; j++) s[i][j] = 0.0f;
        #pragma unroll 16
        for (int kk = 0; kk < 64; kk++) {
            float4 qa = *(const float4*)&Qt[kk * ATT_PAD + ty * 4];
            float4 kb = *(const float4*)&Kt[kk * ATT_PAD + tx * 4];
            float a[4] = {qa.x, qa.y, qa.z, qa.w};
            float c[4] = {kb.x, kb.y, kb.z, kb.w};
            #pragma unroll
            for (int i = 0; i < 4; i++)
                #pragma unroll
                for (int j = 0; j < 4; j++)
                    s[i][j] += a[i] * c[j];
        }
        const float sc = 0.125f;  // 1/sqrt(64)
        bool diag = (kt == qt);
        #pragma unroll
        for (int i = 0; i < 4; i++)
            #pragma unroll
            for (int j = 0; j < 4; j++) {
                s[i][j] *= sc;
                if (diag && (tx * 4 + j) > (ty * 4 + i)) s[i][j] = -1e30f;
            }

        // online softmax (row stats shared across the 16 tx lanes via shfl)
        #pragma unroll
        for (int i = 0; i < 4; i++) {
            float mloc = fmaxf(fmaxf(s[i][0], s[i][1]), fmaxf(s[i][2], s[i][3]));
            #pragma unroll
            for (int off = 8; off; off >>= 1)
                mloc = fmaxf(mloc, __shfl_xor_sync(0xffffffffu, mloc, off));
            float mnew = fmaxf(m[i], mloc);
            float alpha = __expf(m[i] - mnew);
            float rs = 0.0f;
            #pragma unroll
            for (int j = 0; j < 4; j++) {
                float p = __expf(s[i][j] - mnew);
                s[i][j] = p; rs += p;
            }
            #pragma unroll
            for (int off = 8; off; off >>= 1)
                rs += __shfl_xor_sync(0xffffffffu, rs, off);
            l[i] = l[i] * alpha + rs;
            #pragma unroll
            for (int j = 0; j < 4; j++) o[i][j] *= alpha;
            m[i] = mnew;
        }

        // write P tile [query][key]
        #pragma unroll
        for (int i = 0; i < 4; i++) {
            float4 p4 = make_float4(s[i][0], s[i][1], s[i][2], s[i][3]);
            *(float4*)&Ps[(ty * 4 + i) * ATT_PAD + tx * 4] = p4;
        }
        __syncthreads();

        // O += P @ V
        #pragma unroll 16
        for (int kk = 0; kk < 64; kk++) {
            float4 vb = *(const float4*)&Vs[kk * ATT_PAD + tx * 4];
            #pragma unroll
            for (int i = 0; i < 4; i++) {
                float p = Ps[(ty * 4 + i) * ATT_PAD + kk];
                o[i][0] += p * vb.x; o[i][1] += p * vb.y;
                o[i][2] += p * vb.z; o[i][3] += p * vb.w;
            }
        }
    }

    #pragma unroll
    for (int i = 0; i < 4; i++) {
        float inv = 1.0f / l[i];
        float4 ov = make_float4(o[i][0] * inv, o[i][1] * inv, o[i][2] * inv, o[i][3] * inv);
        *(float4*)&O[base + (size_t)(qbase + ty * 4 + i) * D_MODEL + tx * 4] = ov;
    }
}

// -------------------- launch ------------------------------------------------
extern "C" void kernel_launch(void* const* d_in, const int* in_sizes, int n_in,
                              void* d_out, int out_size) {
    const float* x  = (const float*)d_in[0];
    const float* Wq = (const float*)d_in[1];
    const float* bq = (const float*)d_in[2];
    const float* Wk = (const float*)d_in[3];
    const float* bk = (const float*)d_in[4];
    const float* Wv = (const float*)d_in[5];
    const float* bv = (const float*)d_in[6];
    const float* Wo = (const float*)d_in[7];
    const float* bo = (const float*)d_in[8];
    const float* W1 = (const float*)d_in[9];
    const float* b1 = (const float*)d_in[10];
    const float* W2 = (const float*)d_in[11];
    const float* b2 = (const float*)d_in[12];
    const float* ga1 = (const float*)d_in[13];
    const float* be1 = (const float*)d_in[14];
    const float* ga2 = (const float*)d_in[15];
    const float* be2 = (const float*)d_in[16];
    float* out = (float*)d_out;

    float *ln, *q, *k, *v, *ctx, *hb;
    cudaGetSymbolAddress((void**)&ln,  g_ln);
    cudaGetSymbolAddress((void**)&q,   g_q);
    cudaGetSymbolAddress((void**)&k,   g_k);
    cudaGetSymbolAddress((void**)&v,   g_v);
    cudaGetSymbolAddress((void**)&ctx, g_ctx);
    cudaGetSymbolAddress((void**)&hb,  g_h);

    cudaFuncSetAttribute(attn_kernel, cudaFuncAttributeMaxDynamicSharedMemorySize, ATTN_SMEM);

    // 1. LN1
    ln_kernel<<<NROWS, 256>>>(x, ga1, be1, ln);

    // 2. QKV projections
    dim3 gqkv(D_MODEL / BN, NROWS / BM);
    gemm_kernel<false, false><<<gqkv, 256>>>(ln, Wq, bq, nullptr, q, NROWS, D_MODEL, D_MODEL);
    gemm_kernel<false, false><<<gqkv, 256>>>(ln, Wk, bk, nullptr, k, NROWS, D_MODEL, D_MODEL);
    gemm_kernel<false, false><<<gqkv, 256>>>(ln, Wv, bv, nullptr, v, NROWS, D_MODEL, D_MODEL);

    // 3. causal attention
    dim3 ga(SEQ / 64, BATCH * NHEAD);
    attn_kernel<<<ga, 256, ATTN_SMEM>>>(q, k, v, ctx);

    // 4. output projection + residual -> out (= x1)
    gemm_kernel<false, true><<<gqkv, 256>>>(ctx, Wo, bo, x, out, NROWS, D_MODEL, D_MODEL);

    // 5. LN2
    ln_kernel<<<NROWS, 256>>>(out, ga2, be2, ln);

    // 6. MLP up + GELU
    dim3 gup(DFF / BN, NROWS / BM);
    gemm_kernel<true, false><<<gup, 256>>>(ln, W1, b1, nullptr, hb, NROWS, DFF, D_MODEL);

    // 7. MLP down + residual (reads out as residual, writes out; elementwise-safe)
    gemm_kernel<false, true><<<gqkv, 256>>>(hb, W2, b2, out, out, NROWS, D_MODEL, DFF);
}

// round 5
// speedup vs baseline: 1.9654x; 1.9654x over previous
#include <cuda_runtime.h>
#include <math.h>
#include <stdint.h>

#define D_MODEL 1024
#define SEQ     2048
#define BATCH   2
#define NROWS   (BATCH*SEQ)   /* 4096 */
#define DFF     4096
#define NHEAD   16
#define HDIM    64

// -------------------- scratch (device globals; no allocs allowed) ------------
__device__ float g_ln [NROWS*D_MODEL];
__device__ float g_q  [NROWS*D_MODEL];
__device__ float g_k  [NROWS*D_MODEL];
__device__ float g_v  [NROWS*D_MODEL];
__device__ float g_ctx[NROWS*D_MODEL];
__device__ float g_h  [NROWS*DFF];

// ==================== small PTX helpers (portable ISA only) ==================
__device__ __forceinline__ uint32_t smem_u32(const void* p) {
    uint32_t a;
    asm("{ .reg .u64 t; cvta.to.shared.u64 t, %1; cvt.u32.u64 %0, t; }" : "=r"(a) : "l"(p));
    return a;
}
__device__ __forceinline__ void cp_async16(uint32_t dst, const void* src) {
    asm volatile("cp.async.cg.shared.global [%0], [%1], 16;" :: "r"(dst), "l"(src));
}
#define CP_COMMIT()  asm volatile("cp.async.commit_group;" ::: "memory")
#define CP_WAIT(n)   asm volatile("cp.async.wait_group %0;" :: "n"(n) : "memory")

__device__ __forceinline__ uint32_t f2tf32(float x) {
    uint32_t r; asm("cvt.rna.tf32.f32 %0, %1;" : "=r"(r) : "f"(x)); return r;
}
// m16n8k8 tf32 MMA (portable sm_80+ ISA; works on family target sm_103)
__device__ __forceinline__ void mma_tf32(float* c, const uint32_t* a, const uint32_t* b) {
    asm volatile("mma.sync.aligned.m16n8k8.row.col.f32.tf32.tf32.f32 "
        "{%0,%1,%2,%3}, {%4,%5,%6,%7}, {%8,%9}, {%0,%1,%2,%3};"
        : "+f"(c[0]), "+f"(c[1]), "+f"(c[2]), "+f"(c[3])
        : "r"(a[0]), "r"(a[1]), "r"(a[2]), "r"(a[3]), "r"(b[0]), "r"(b[1]));
}

// -------------------- LayerNorm (ddof=1, eps=1e-12) --------------------------
__device__ __forceinline__ float blockSum(float v, float* red, int tid) {
    #pragma unroll
    for (int o = 16; o; o >>= 1) v += __shfl_xor_sync(0xffffffffu, v, o);
    if ((tid & 31) == 0) red[tid >> 5] = v;
    __syncthreads();
    if (tid < 8) {
        v = red[tid];
        #pragma unroll
        for (int o = 4; o; o >>= 1) v += __shfl_xor_sync(0xffu, v, o);
        if (tid == 0) red[0] = v;
    }
    __syncthreads();
    float r = red[0];
    __syncthreads();
    return r;
}

__global__ void ln_kernel(const float* __restrict__ x,
                          const float* __restrict__ gamma,
                          const float* __restrict__ beta,
                          float* __restrict__ y) {
    __shared__ float red[8];
    int row = blockIdx.x, tid = threadIdx.x;
    const float4* x4 = (const float4*)(x + (size_t)row * D_MODEL);
    float4 v = x4[tid];
    float s = v.x + v.y + v.z + v.w;
    float tot = blockSum(s, red, tid);
    float mean = tot * (1.0f / D_MODEL);
    float dx0 = v.x - mean, dx1 = v.y - mean, dx2 = v.z - mean, dx3 = v.w - mean;
    float sq = dx0*dx0 + dx1*dx1 + dx2*dx2 + dx3*dx3;
    float tots = blockSum(sq, red, tid);
    float var = tots * (1.0f / (D_MODEL - 1));    // ddof = 1
    float inv = rsqrtf(var + 1e-12f);
    float4 gv = ((const float4*)gamma)[tid];
    float4 bv = ((const float4*)beta)[tid];
    float4 o;
    o.x = gv.x * dx0 * inv + bv.x;
    o.y = gv.y * dx1 * inv + bv.y;
    o.z = gv.z * dx2 * inv + bv.z;
    o.w = gv.w * dx3 * inv + bv.w;
    ((float4*)(y + (size_t)row * D_MODEL))[tid] = o;
}

// ==================== tensor-core tf32 GEMM via mma.sync ====================
// C[M,N] = A[M,K] @ B[K,N] + bias (+gelu)(+res).
// 128x128 tile/CTA, BK=16, 8 warps (2m x 4n), warp tile 64x32.
#define BM 128
#define BN 128
#define BK 16
#define ASTR (BK + 4)    /* 20 floats: (gid*20+tig)%32 distinct over warp */
#define BSTR (BN + 4)    /* 132 floats: (tig*132+gid)%32 distinct over warp */

__device__ __forceinline__ float gelu_f(float x) {
    float x3 = x * x * x;
    return 0.5f * x * (1.0f + tanhf(0.7978845608028654f * (x + 0.044715f * x3)));
}

template<bool GELU, bool RES>
__global__ void __launch_bounds__(256)
mma_gemm(const float* __restrict__ A, const float* __restrict__ Bm,
         const float* __restrict__ bias, const float* __restrict__ res,
         float* __restrict__ C, int M, int N, int K) {
    __shared__ float As[2][BM][ASTR];   // [m][k]   20,480 B
    __shared__ float Bs[2][BK][BSTR];   // [k][n]   16,896 B
    const int tid  = threadIdx.x;
    const int wid  = tid >> 5, lane = tid & 31;
    const int gid  = lane >> 2, tig = lane & 3;
    const int wm0  = (wid & 1) * 64;
    const int wn0  = (wid >> 1) * 32;
    const int row0 = blockIdx.y * BM, col0 = blockIdx.x * BN;

    float acc[4][4][4];
    #pragma unroll
    for (int i = 0; i < 4; i++)
        #pragma unroll
        for (int j = 0; j < 4; j++)
            #pragma unroll
            for (int h = 0; h < 4; h++) acc[i][j][h] = 0.0f;

    auto load_tiles = [&](int buf, int k0) {
        #pragma unroll
        for (int i = 0; i < 2; i++) {           // A: 128 rows x 64B = 512 x 16B
            int idx = tid + i * 256;
            int r = idx >> 2, kc = (idx & 3) << 2;
            cp_async16(smem_u32(&As[buf][r][kc]),
                       &A[(size_t)(row0 + r) * K + k0 + kc]);
        }
        #pragma unroll
        for (int i = 0; i < 2; i++) {           // B: 16 rows x 512B = 512 x 16B
            int idx = tid + i * 256;
            int kr = idx >> 5, nc = (idx & 31) << 2;
            cp_async16(smem_u32(&Bs[buf][kr][nc]),
                       &Bm[(size_t)(k0 + kr) * N + col0 + nc]);
        }
        CP_COMMIT();
    };

    load_tiles(0, 0);
    const int nsteps = K >> 4;

    for (int s = 0; s < nsteps; s++) {
        const int buf = s & 1;
        if (s + 1 < nsteps) { load_tiles(buf ^ 1, (s + 1) << 4); CP_WAIT(1); }
        else                { CP_WAIT(0); }
        __syncthreads();

        #pragma unroll
        for (int ks = 0; ks < 2; ks++) {
            const int kb = ks * 8;
            uint32_t af[4][4], bf[4][2];
            #pragma unroll
            for (int mi = 0; mi < 4; mi++) {
                const int m = wm0 + mi * 16 + gid;
                af[mi][0] = f2tf32(As[buf][m    ][kb + tig]);
                af[mi][1] = f2tf32(As[buf][m + 8][kb + tig]);
                af[mi][2] = f2tf32(As[buf][m    ][kb + tig + 4]);
                af[mi][3] = f2tf32(As[buf][m + 8][kb + tig + 4]);
            }
            #pragma unroll
            for (int ni = 0; ni < 4; ni++) {
                const int n = wn0 + ni * 8 + gid;
                bf[ni][0] = f2tf32(Bs[buf][kb + tig    ][n]);
                bf[ni][1] = f2tf32(Bs[buf][kb + tig + 4][n]);
            }
            #pragma unroll
            for (int mi = 0; mi < 4; mi++)
                #pragma unroll
                for (int ni = 0; ni < 4; ni++)
                    mma_tf32(acc[mi][ni], af[mi], bf[ni]);
        }
        __syncthreads();
    }

    // -------- epilogue: bias (+gelu)(+res), float2 stores --------------------
    #pragma unroll
    for (int mi = 0; mi < 4; mi++) {
        #pragma unroll
        for (int ni = 0; ni < 4; ni++) {
            const int c = col0 + wn0 + ni * 8 + tig * 2;
            const float2 bv = *(const float2*)&bias[c];
            #pragma unroll
            for (int h = 0; h < 2; h++) {
                const int r = row0 + wm0 + mi * 16 + gid + h * 8;
                float2 o;
                o.x = acc[mi][ni][h * 2 + 0] + bv.x;
                o.y = acc[mi][ni][h * 2 + 1] + bv.y;
                if (GELU) { o.x = gelu_f(o.x); o.y = gelu_f(o.y); }
                if (RES) {
                    float2 rr = *(const float2*)&res[(size_t)r * N + c];
                    o.x += rr.x; o.y += rr.y;
                }
                *(float2*)&C[(size_t)r * N + c] = o;
            }
        }
    }
}

// -------------------- causal flash attention, fp32, 64q x 64k tiles ----------
#define ATT_PAD 68
#define ATTN_SMEM (4 * 64 * ATT_PAD * (int)sizeof(float))

__global__ void __launch_bounds__(256)
attn_kernel(const float* __restrict__ Q, const float* __restrict__ K,
            const float* __restrict__ V, float* __restrict__ O) {
    extern __shared__ float sm[];
    float* Qt = sm;                     // [dim][query]  64 x 68
    float* Kt = sm + 64 * ATT_PAD;      // [dim][key]
    float* Vs = sm + 2 * 64 * ATT_PAD;  // [key][dim]
    float* Ps = sm + 3 * 64 * ATT_PAD;  // [query][key]

    int tid = threadIdx.x;
    int tx = tid & 15, ty = tid >> 4;
    int qt = blockIdx.x, bh = blockIdx.y;
    int b = bh >> 4, h = bh & 15;
    size_t base = (size_t)b * SEQ * D_MODEL + (size_t)h * HDIM;
    int qbase = qt * 64;

    #pragma unroll
    for (int t = 0; t < 4; t++) {
        int f = tid + t * 256;
        int r = f >> 4, cv = (f & 15) << 2;
        float4 q = *(const float4*)&Q[base + (size_t)(qbase + r) * D_MODEL + cv];
        Qt[(cv + 0) * ATT_PAD + r] = q.x; Qt[(cv + 1) * ATT_PAD + r] = q.y;
        Qt[(cv + 2) * ATT_PAD + r] = q.z; Qt[(cv + 3) * ATT_PAD + r] = q.w;
    }

    float m[4], l[4], o[4][4];
    #pragma unroll
    for (int i = 0; i < 4; i++) {
        m[i] = -1e30f; l[i] = 0.0f;
        #pragma unroll
        for (int j = 0; j < 4; j++) o[i][j] = 0.0f;
    }

    for (int kt = 0; kt <= qt; kt++) {
        int kbase = kt * 64;
        __syncthreads();
        #pragma unroll
        for (int t = 0; t < 4; t++) {
            int f = tid + t * 256;
            int r = f >> 4, cv = (f & 15) << 2;
            float4 kv = *(const float4*)&K[base + (size_t)(kbase + r) * D_MODEL + cv];
            Kt[(cv + 0) * ATT_PAD + r] = kv.x; Kt[(cv + 1) * ATT_PAD + r] = kv.y;
            Kt[(cv + 2) * ATT_PAD + r] = kv.z; Kt[(cv + 3) * ATT_PAD + r] = kv.w;
            float4 vv = *(const float4*)&V[base + (size_t)(kbase + r) * D_MODEL + cv];
            *(float4*)&Vs[r * ATT_PAD + cv] = vv;
        }
        __syncthreads();

        float s[4][4];
        #pragma unroll
        for (int i = 0; i < 4; i++)
            #pragma unroll
            for (int j = 0; j < 4; j++) s[i][j] = 0.0f;
        #pragma unroll 16
        for (int kk = 0; kk < 64; kk++) {
            float4 qa = *(const float4*)&Qt[kk * ATT_PAD + ty * 4];
            float4 kb = *(const float4*)&Kt[kk * ATT_PAD + tx * 4];
            float a[4] = {qa.x, qa.y, qa.z, qa.w};
            float c[4] = {kb.x, kb.y, kb.z, kb.w};
            #pragma unroll
            for (int i = 0; i < 4; i++)
                #pragma unroll
                for (int j = 0; j < 4; j++)
                    s[i][j] += a[i] * c[j];
        }
        const float sc = 0.125f;  // 1/sqrt(64)
        bool diag = (kt == qt);
        #pragma unroll
        for (int i = 0; i < 4; i++)
            #pragma unroll
            for (int j = 0; j < 4; j++) {
                s[i][j] *= sc;
                if (diag && (tx * 4 + j) > (ty * 4 + i)) s[i][j] = -1e30f;
            }

        #pragma unroll
        for (int i = 0; i < 4; i++) {
            float mloc = fmaxf(fmaxf(s[i][0], s[i][1]), fmaxf(s[i][2], s[i][3]));
            #pragma unroll
            for (int off = 8; off; off >>= 1)
                mloc = fmaxf(mloc, __shfl_xor_sync(0xffffffffu, mloc, off));
            float mnew = fmaxf(m[i], mloc);
            float alpha = __expf(m[i] - mnew);
            float rs = 0.0f;
            #pragma unroll
            for (int j = 0; j < 4; j++) {
                float p = __expf(s[i][j] - mnew);
                s[i][j] = p; rs += p;
            }
            #pragma unroll
            for (int off = 8; off; off >>= 1)
                rs += __shfl_xor_sync(0xffffffffu, rs, off);
            l[i] = l[i] * alpha + rs;
            #pragma unroll
            for (int j = 0; j < 4; j++) o[i][j] *= alpha;
            m[i] = mnew;
        }

        #pragma unroll
        for (int i = 0; i < 4; i++) {
            float4 p4 = make_float4(s[i][0], s[i][1], s[i][2], s[i][3]);
            *(float4*)&Ps[(ty * 4 + i) * ATT_PAD + tx * 4] = p4;
        }
        __syncthreads();

        #pragma unroll 16
        for (int kk = 0; kk < 64; kk++) {
            float4 vb = *(const float4*)&Vs[kk * ATT_PAD + tx * 4];
            #pragma unroll
            for (int i = 0; i < 4; i++) {
                float p = Ps[(ty * 4 + i) * ATT_PAD + kk];
                o[i][0] += p * vb.x; o[i][1] += p * vb.y;
                o[i][2] += p * vb.z; o[i][3] += p * vb.w;
            }
        }
    }

    #pragma unroll
    for (int i = 0; i < 4; i++) {
        float inv = 1.0f / l[i];
        float4 ov = make_float4(o[i][0] * inv, o[i][1] * inv, o[i][2] * inv, o[i][3] * inv);
        *(float4*)&O[base + (size_t)(qbase + ty * 4 + i) * D_MODEL + tx * 4] = ov;
    }
}

// -------------------- launch ------------------------------------------------
extern "C" void kernel_launch(void* const* d_in, const int* in_sizes, int n_in,
                              void* d_out, int out_size) {
    const float* x  = (const float*)d_in[0];
    const float* Wq = (const float*)d_in[1];
    const float* bq = (const float*)d_in[2];
    const float* Wk = (const float*)d_in[3];
    const float* bk = (const float*)d_in[4];
    const float* Wv = (const float*)d_in[5];
    const float* bv = (const float*)d_in[6];
    const float* Wo = (const float*)d_in[7];
    const float* bo = (const float*)d_in[8];
    const float* W1 = (const float*)d_in[9];
    const float* b1 = (const float*)d_in[10];
    const float* W2 = (const float*)d_in[11];
    const float* b2 = (const float*)d_in[12];
    const float* ga1 = (const float*)d_in[13];
    const float* be1 = (const float*)d_in[14];
    const float* ga2 = (const float*)d_in[15];
    const float* be2 = (const float*)d_in[16];
    float* out = (float*)d_out;

    float *ln, *q, *k, *v, *ctx, *hb;
    cudaGetSymbolAddress((void**)&ln,  g_ln);
    cudaGetSymbolAddress((void**)&q,   g_q);
    cudaGetSymbolAddress((void**)&k,   g_k);
    cudaGetSymbolAddress((void**)&v,   g_v);
    cudaGetSymbolAddress((void**)&ctx, g_ctx);
    cudaGetSymbolAddress((void**)&hb,  g_h);

    cudaFuncSetAttribute(attn_kernel, cudaFuncAttributeMaxDynamicSharedMemorySize, ATTN_SMEM);

    // 1. LN1
    ln_kernel<<<NROWS, 256>>>(x, ga1, be1, ln);

    // 2. QKV projections
    dim3 gqkv(D_MODEL / BN, NROWS / BM);
    mma_gemm<false,false><<<gqkv, 256>>>(ln, Wq, bq, nullptr, q, NROWS, D_MODEL, D_MODEL);
    mma_gemm<false,false><<<gqkv, 256>>>(ln, Wk, bk, nullptr, k, NROWS, D_MODEL, D_MODEL);
    mma_gemm<false,false><<<gqkv, 256>>>(ln, Wv, bv, nullptr, v, NROWS, D_MODEL, D_MODEL);

    // 3. causal attention
    dim3 ga(SEQ / 64, BATCH * NHEAD);
    attn_kernel<<<ga, 256, ATTN_SMEM>>>(q, k, v, ctx);

    // 4. output projection + residual -> out
    mma_gemm<false,true><<<gqkv, 256>>>(ctx, Wo, bo, x, out, NROWS, D_MODEL, D_MODEL);

    // 5. LN2
    ln_kernel<<<NROWS, 256>>>(out, ga2, be2, ln);

    // 6. MLP up + GELU
    dim3 gup(DFF / BN, NROWS / BM);
    mma_gemm<true,false><<<gup, 256>>>(ln, W1, b1, nullptr, hb, NROWS, DFF, D_MODEL);

    // 7. MLP down + residual
    mma_gemm<false,true><<<gqkv, 256>>>(hb, W2, b2, out, out, NROWS, D_MODEL, DFF);
}